// round 9
// baseline (speedup 1.0000x reference)
#include <cuda_runtime.h>
#include <cuda_bf16.h>

#define T_STEPS 512
#define HID 32
#define IN_SZ 8

__device__ __forceinline__ float sigmoid_fast(float x) {
    // 1 / (1 + e^-x) via MUFU.EX2 + MUFU.RCP; rel err ~2^-22, fine vs 1e-3 gate
    return __fdividef(1.0f, 1.0f + __expf(-x));
}
__device__ __forceinline__ float tanh_fast(float x) {
    // tanh(x) = 2/(1+e^-2x) - 1 ; absolute error ~1e-7, safe through the scan
    return __fdividef(2.0f, 1.0f + __expf(-2.0f * x)) - 1.0f;
}

__global__ __launch_bounds__(128)
void lstm_warp_kernel(
    const float* __restrict__ x,     // [B, T, 8]
    const float* __restrict__ W_ih,  // [128, 8]
    const float* __restrict__ W_hh,  // [128, 32]
    const float* __restrict__ b_ih,  // [128]
    const float* __restrict__ b_hh,  // [128]
    const float* __restrict__ W_fc,  // [1, 32]
    const float* __restrict__ b_fc,  // [1]
    float* __restrict__ out,         // [B] (logical [1,B,1])
    int B)
{
    const int warp = blockIdx.x * (blockDim.x >> 5) + (threadIdx.x >> 5);
    const int lane = threadIdx.x & 31;
    if (warp >= B) return;

    // ---- per-lane register-resident weights (lane j owns hidden unit j) ----
    // PyTorch gate order i,f,g,o: row(g, j) = g*32 + j
    float whh[4][HID];
    float wih[4][IN_SZ];
    float bias[4];
#pragma unroll
    for (int g = 0; g < 4; g++) {
        const int row = g * HID + lane;
        bias[g] = b_ih[row] + b_hh[row];
#pragma unroll
        for (int d = 0; d < IN_SZ; d++) wih[g][d] = W_ih[row * IN_SZ + d];
#pragma unroll
        for (int k = 0; k < HID; k++) whh[g][k] = W_hh[row * HID + k];
    }

    const float4* xp = reinterpret_cast<const float4*>(
        x + (size_t)warp * ((size_t)T_STEPS * IN_SZ));

    float h = 0.0f, c = 0.0f;
    // software-pipeline the tiny x load (32B/step) to hide DRAM latency
    float4 xa = xp[0];
    float4 xb = xp[1];

#pragma unroll 1
    for (int t = 0; t < T_STEPS; t++) {
        float4 na = xa, nb = xb;
        if (t + 1 < T_STEPS) {
            na = xp[2 * t + 2];
            nb = xp[2 * t + 3];
        }

        float a0 = bias[0], a1 = bias[1], a2 = bias[2], a3 = bias[3];

        // input contribution: 4 gates x 8 inputs
        const float xv[8] = {xa.x, xa.y, xa.z, xa.w, xb.x, xb.y, xb.z, xb.w};
#pragma unroll
        for (int d = 0; d < IN_SZ; d++) {
            a0 = fmaf(wih[0][d], xv[d], a0);
            a1 = fmaf(wih[1][d], xv[d], a1);
            a2 = fmaf(wih[2][d], xv[d], a2);
            a3 = fmaf(wih[3][d], xv[d], a3);
        }

        // recurrence: h broadcast via shuffle, 4 independent FMA chains (ILP=4)
#pragma unroll
        for (int k = 0; k < HID; k++) {
            const float hk = __shfl_sync(0xffffffffu, h, k);
            a0 = fmaf(whh[0][k], hk, a0);
            a1 = fmaf(whh[1][k], hk, a1);
            a2 = fmaf(whh[2][k], hk, a2);
            a3 = fmaf(whh[3][k], hk, a3);
        }

        const float ig = sigmoid_fast(a0);
        const float fg = sigmoid_fast(a1);
        const float gg = tanh_fast(a2);
        const float og = sigmoid_fast(a3);
        c = fmaf(fg, c, ig * gg);
        h = og * tanh_fast(c);

        xa = na; xb = nb;
    }

    // ---- final FC: out[b] = sum_j h_j * W_fc[j] + b_fc ----
    float v = h * W_fc[lane];
#pragma unroll
    for (int off = 16; off; off >>= 1)
        v += __shfl_xor_sync(0xffffffffu, v, off);
    if (lane == 0) out[warp] = v + b_fc[0];
}

extern "C" void kernel_launch(void* const* d_in, const int* in_sizes, int n_in,
                              void* d_out, int out_size) {
    const float* x    = (const float*)d_in[0];
    const float* W_ih = (const float*)d_in[1];
    const float* W_hh = (const float*)d_in[2];
    const float* b_ih = (const float*)d_in[3];
    const float* b_hh = (const float*)d_in[4];
    const float* W_fc = (const float*)d_in[5];
    const float* b_fc = (const float*)d_in[6];
    float* out = (float*)d_out;

    const int B = in_sizes[0] / (T_STEPS * IN_SZ);   // 8192
    const int warpsPerBlock = 4;                     // 128 threads
    const int blocks = (B + warpsPerBlock - 1) / warpsPerBlock;
    lstm_warp_kernel<<<blocks, warpsPerBlock * 32>>>(
        x, W_ih, W_hh, b_ih, b_hh, W_fc, b_fc, out, B);
}

// round 10
// speedup vs baseline: 1.0793x; 1.0793x over previous
#include <cuda_runtime.h>
#include <cuda_bf16.h>

#define T_STEPS 512
#define HID 32
#define IN_SZ 8

typedef unsigned long long u64;

__device__ __forceinline__ u64 pack2(float lo, float hi) {
    u64 r; asm("mov.b64 %0, {%1, %2};" : "=l"(r) : "f"(lo), "f"(hi)); return r;
}
__device__ __forceinline__ void unpack2(u64 v, float& lo, float& hi) {
    asm("mov.b64 {%0, %1}, %2;" : "=f"(lo), "=f"(hi) : "l"(v));
}
// Blackwell packed fp32 FMA: one FMA-pipe slot, two MACs.
__device__ __forceinline__ u64 fma2(u64 a, u64 b, u64 c) {
    u64 d; asm("fma.rn.f32x2 %0, %1, %2, %3;" : "=l"(d) : "l"(a), "l"(b), "l"(c));
    return d;
}

__device__ __forceinline__ float sigmoid_fast(float x) {
    return __fdividef(1.0f, 1.0f + __expf(-x));
}
__device__ __forceinline__ float tanh_fast(float x) {
    return __fdividef(2.0f, 1.0f + __expf(-2.0f * x)) - 1.0f;
}

__global__ __launch_bounds__(128)
void lstm_warp_kernel(
    const float* __restrict__ x,     // [B, T, 8]
    const float* __restrict__ W_ih,  // [128, 8]
    const float* __restrict__ W_hh,  // [128, 32]
    const float* __restrict__ b_ih,  // [128]
    const float* __restrict__ b_hh,  // [128]
    const float* __restrict__ W_fc,  // [1, 32]
    const float* __restrict__ b_fc,  // [1]
    float* __restrict__ out,         // [B]
    int B)
{
    // per-warp double-buffered h broadcast staging (128B per buffer -> LDS.64 pairs)
    __shared__ float hbuf[4][2][HID];

    const int wib  = threadIdx.x >> 5;
    const int warp = blockIdx.x * 4 + wib;
    const int lane = threadIdx.x & 31;
    if (warp >= B) return;

    // ---- register-resident packed weights: lane j owns hidden unit j ----
    // gate order i,f,g,o : row(g,j) = g*32 + j. Rows are contiguous, so
    // k-pairs load directly as 64-bit words (no repacking).
    u64 whhp[4][HID / 2];   // {W[row][2k], W[row][2k+1]}
    u64 wihp[4][IN_SZ / 2];
    u64 biasp[4];
    const u64* whh64 = reinterpret_cast<const u64*>(W_hh);
    const u64* wih64 = reinterpret_cast<const u64*>(W_ih);
#pragma unroll
    for (int g = 0; g < 4; g++) {
        const int row = g * HID + lane;
        biasp[g] = pack2(b_ih[row] + b_hh[row], 0.0f);  // bias in lo half only
#pragma unroll
        for (int d = 0; d < IN_SZ / 2; d++) wihp[g][d] = wih64[row * (IN_SZ / 2) + d];
#pragma unroll
        for (int k = 0; k < HID / 2; k++)  whhp[g][k] = whh64[row * (HID / 2) + k];
    }

    const ulonglong2* xp = reinterpret_cast<const ulonglong2*>(
        x + (size_t)warp * ((size_t)T_STEPS * IN_SZ));

    float h = 0.0f, c = 0.0f;
    ulonglong2 xc0 = xp[0], xc1 = xp[1];   // software-pipelined x (32B/step)

#pragma unroll 1
    for (int t = 0; t < T_STEPS; t++) {
        ulonglong2 xn0 = xc0, xn1 = xc1;
        if (t + 1 < T_STEPS) { xn0 = xp[2 * t + 2]; xn1 = xp[2 * t + 3]; }

        // broadcast h through smem: 1 STS + 16 uniform LDS.64 (pairs pre-packed)
        float* hb = hbuf[wib][t & 1];
        hb[lane] = h;
        __syncwarp();

        // f32x2 accumulators: {even-k partial, odd-k partial} per gate
        u64 a0 = biasp[0], a1 = biasp[1], a2 = biasp[2], a3 = biasp[3];

        // input contribution: x pairs are contiguous -> already packed
        const u64 xv[4] = {xc0.x, xc0.y, xc1.x, xc1.y};
#pragma unroll
        for (int d = 0; d < IN_SZ / 2; d++) {
            a0 = fma2(wihp[0][d], xv[d], a0);
            a1 = fma2(wihp[1][d], xv[d], a1);
            a2 = fma2(wihp[2][d], xv[d], a2);
            a3 = fma2(wihp[3][d], xv[d], a3);
        }

        // recurrence: 16 pair-iterations, 4 independent FMA2 chains
        const u64* hp = reinterpret_cast<const u64*>(hb);
#pragma unroll
        for (int k = 0; k < HID / 2; k++) {
            const u64 hk = hp[k];
            a0 = fma2(whhp[0][k], hk, a0);
            a1 = fma2(whhp[1][k], hk, a1);
            a2 = fma2(whhp[2][k], hk, a2);
            a3 = fma2(whhp[3][k], hk, a3);
        }

        float i0, i1, f0, f1, g0, g1, o0, o1;
        unpack2(a0, i0, i1);
        unpack2(a1, f0, f1);
        unpack2(a2, g0, g1);
        unpack2(a3, o0, o1);

        const float ig = sigmoid_fast(i0 + i1);
        const float fg = sigmoid_fast(f0 + f1);
        const float gg = tanh_fast(g0 + g1);
        const float og = sigmoid_fast(o0 + o1);
        c = fmaf(fg, c, ig * gg);
        h = og * tanh_fast(c);

        xc0 = xn0; xc1 = xn1;
    }

    // ---- final FC ----
    float v = h * W_fc[lane];
#pragma unroll
    for (int off = 16; off; off >>= 1)
        v += __shfl_xor_sync(0xffffffffu, v, off);
    if (lane == 0) out[warp] = v + b_fc[0];
}

extern "C" void kernel_launch(void* const* d_in, const int* in_sizes, int n_in,
                              void* d_out, int out_size) {
    const float* x    = (const float*)d_in[0];
    const float* W_ih = (const float*)d_in[1];
    const float* W_hh = (const float*)d_in[2];
    const float* b_ih = (const float*)d_in[3];
    const float* b_hh = (const float*)d_in[4];
    const float* W_fc = (const float*)d_in[5];
    const float* b_fc = (const float*)d_in[6];
    float* out = (float*)d_out;

    const int B = in_sizes[0] / (T_STEPS * IN_SZ);   // 8192
    const int blocks = (B + 3) / 4;                  // 4 warps / block
    lstm_warp_kernel<<<blocks, 128>>>(x, W_ih, W_hh, b_ih, b_hh, W_fc, b_fc, out, B);
}

// round 12
// speedup vs baseline: 1.2181x; 1.1287x over previous
#include <cuda_runtime.h>
#include <cuda_bf16.h>
#include <cstdint>

#define T_STEPS 512
#define HID 32
#define IN_SZ 8
#define CH 8                      // steps per x chunk (256 B / warp)
#define NCHUNK (T_STEPS / CH)     // 64

typedef unsigned long long u64;
typedef unsigned int u32;

__device__ __forceinline__ u64 pack2(float lo, float hi) {
    u64 r; asm("mov.b64 %0, {%1, %2};" : "=l"(r) : "f"(lo), "f"(hi)); return r;
}
__device__ __forceinline__ void unpack2(u64 v, float& lo, float& hi) {
    asm("mov.b64 {%0, %1}, %2;" : "=f"(lo), "=f"(hi) : "l"(v));
}
// Blackwell packed fp32 FMA: one FMA-pipe slot, two MACs.
__device__ __forceinline__ u64 fma2(u64 a, u64 b, u64 c) {
    u64 d; asm("fma.rn.f32x2 %0, %1, %2, %3;" : "=l"(d) : "l"(a), "l"(b), "l"(c));
    return d;
}

__device__ __forceinline__ u32 smem_u32(const void* p) {
    u32 a;
    asm("{ .reg .u64 t; cvta.to.shared.u64 t, %1; cvt.u32.u64 %0, t; }"
        : "=r"(a) : "l"(p));
    return a;
}
__device__ __forceinline__ void cp_async8(u32 dst, const void* src) {
    asm volatile("cp.async.ca.shared.global [%0], [%1], 8;" :: "r"(dst), "l"(src));
}

__device__ __forceinline__ float sigmoid_fast(float x) {
    return __fdividef(1.0f, 1.0f + __expf(-x));
}
__device__ __forceinline__ float tanh_fast(float x) {
    return __fdividef(2.0f, 1.0f + __expf(-2.0f * x)) - 1.0f;
}

__global__ __launch_bounds__(128)
void lstm_warp_kernel(
    const float* __restrict__ x,     // [B, T, 8]
    const float* __restrict__ W_ih,  // [128, 8]
    const float* __restrict__ W_hh,  // [128, 32]
    const float* __restrict__ b_ih,  // [128]
    const float* __restrict__ b_hh,  // [128]
    const float* __restrict__ W_fc,  // [1, 32]
    const float* __restrict__ b_fc,  // [1]
    float* __restrict__ out,         // [B]
    int B)
{
    // x staging: per warp, double-buffered 8-step chunks (256 B each)
    __shared__ __align__(16) float xs[4][2][CH * IN_SZ];
    // h broadcast staging, double-buffered per step parity
    __shared__ __align__(8) float hbuf[4][2][HID];

    const int wib  = threadIdx.x >> 5;
    const int warp = blockIdx.x * 4 + wib;
    const int lane = threadIdx.x & 31;
    if (warp >= B) return;

    // ---- register-resident packed weights: lane j owns hidden unit j ----
    u64 whhp[4][HID / 2];
    u64 wihp[4][IN_SZ / 2];
    u64 biasp[4];
    const u64* whh64 = reinterpret_cast<const u64*>(W_hh);
    const u64* wih64 = reinterpret_cast<const u64*>(W_ih);
#pragma unroll
    for (int g = 0; g < 4; g++) {
        const int row = g * HID + lane;
        biasp[g] = pack2(b_ih[row] + b_hh[row], 0.0f);
#pragma unroll
        for (int d = 0; d < IN_SZ / 2; d++) wihp[g][d] = wih64[row * (IN_SZ / 2) + d];
#pragma unroll
        for (int k = 0; k < HID / 2; k++)  whhp[g][k] = whh64[row * (HID / 2) + k];
    }

    // per-lane global source: 8 B per lane covers one 256 B chunk per warp
    const float* xw = x + (size_t)warp * ((size_t)T_STEPS * IN_SZ);

    // ---- prologue: prefetch chunks 0 and 1 ----
    {
        u32 d0 = smem_u32(&xs[wib][0][lane * 2]);
        cp_async8(d0, xw + 0 * (CH * IN_SZ) + lane * 2);
        asm volatile("cp.async.commit_group;");
        u32 d1 = smem_u32(&xs[wib][1][lane * 2]);
        cp_async8(d1, xw + 1 * (CH * IN_SZ) + lane * 2);
        asm volatile("cp.async.commit_group;");
    }

    float h = 0.0f, c = 0.0f;
    int t = 0;

#pragma unroll 1
    for (int ck = 0; ck < NCHUNK; ck++) {
        asm volatile("cp.async.wait_group 1;");   // chunk ck has landed
        __syncwarp();
        const u64* xb = reinterpret_cast<const u64*>(xs[wib][ck & 1]);

#pragma unroll
        for (int s = 0; s < CH; s++, t++) {
            // broadcast h through smem
            float* hb = hbuf[wib][t & 1];
            hb[lane] = h;
            __syncwarp();

            u64 a0 = biasp[0], a1 = biasp[1], a2 = biasp[2], a3 = biasp[3];

            // input contribution: broadcast LDS.64 pairs, already packed
#pragma unroll
            for (int d = 0; d < IN_SZ / 2; d++) {
                const u64 xv = xb[s * (IN_SZ / 2) + d];
                a0 = fma2(wihp[0][d], xv, a0);
                a1 = fma2(wihp[1][d], xv, a1);
                a2 = fma2(wihp[2][d], xv, a2);
                a3 = fma2(wihp[3][d], xv, a3);
            }

            // recurrence: 16 pair iterations, 4 independent FMA2 chains
            const u64* hp = reinterpret_cast<const u64*>(hb);
#pragma unroll
            for (int k = 0; k < HID / 2; k++) {
                const u64 hk = hp[k];
                a0 = fma2(whhp[0][k], hk, a0);
                a1 = fma2(whhp[1][k], hk, a1);
                a2 = fma2(whhp[2][k], hk, a2);
                a3 = fma2(whhp[3][k], hk, a3);
            }

            float i0, i1, f0, f1, g0, g1, o0, o1;
            unpack2(a0, i0, i1);
            unpack2(a1, f0, f1);
            unpack2(a2, g0, g1);
            unpack2(a3, o0, o1);

            const float ig = sigmoid_fast(i0 + i1);
            const float fg = sigmoid_fast(f0 + f1);
            const float gg = tanh_fast(g0 + g1);
            const float og = sigmoid_fast(o0 + o1);
            c = fmaf(fg, c, ig * gg);
            h = og * tanh_fast(c);
        }

        // prefetch chunk ck+2 into the buffer we just finished reading
        if (ck + 2 < NCHUNK) {
            u32 dst = smem_u32(&xs[wib][ck & 1][lane * 2]);
            cp_async8(dst, xw + (ck + 2) * (CH * IN_SZ) + lane * 2);
        }
        asm volatile("cp.async.commit_group;");   // commit (possibly empty) group
    }

    // ---- final FC ----
    float v = h * W_fc[lane];
#pragma unroll
    for (int off = 16; off; off >>= 1)
        v += __shfl_xor_sync(0xffffffffu, v, off);
    if (lane == 0) out[warp] = v + b_fc[0];
}

extern "C" void kernel_launch(void* const* d_in, const int* in_sizes, int n_in,
                              void* d_out, int out_size) {
    const float* x    = (const float*)d_in[0];
    const float* W_ih = (const float*)d_in[1];
    const float* W_hh = (const float*)d_in[2];
    const float* b_ih = (const float*)d_in[3];
    const float* b_hh = (const float*)d_in[4];
    const float* W_fc = (const float*)d_in[5];
    const float* b_fc = (const float*)d_in[6];
    float* out = (float*)d_out;

    const int B = in_sizes[0] / (T_STEPS * IN_SZ);   // 8192
    const int blocks = (B + 3) / 4;                  // 4 warps / block
    lstm_warp_kernel<<<blocks, 128>>>(x, W_ih, W_hh, b_ih, b_hh, W_fc, b_fc, out, B);
}

// round 13
// speedup vs baseline: 1.2579x; 1.0326x over previous
#include <cuda_runtime.h>
#include <cuda_bf16.h>
#include <cstdint>

#define T_STEPS 512
#define HID 32
#define IN_SZ 8
#define CH 8                      // steps per x chunk (256 B / warp)
#define NCHUNK (T_STEPS / CH)     // 64

typedef unsigned long long u64;
typedef unsigned int u32;

__device__ __forceinline__ u64 pack2(float lo, float hi) {
    u64 r; asm("mov.b64 %0, {%1, %2};" : "=l"(r) : "f"(lo), "f"(hi)); return r;
}
__device__ __forceinline__ void unpack2(u64 v, float& lo, float& hi) {
    asm("mov.b64 {%0, %1}, %2;" : "=f"(lo), "=f"(hi) : "l"(v));
}
// Blackwell packed fp32 FMA: one FMA-pipe slot, two MACs.
__device__ __forceinline__ u64 fma2(u64 a, u64 b, u64 c) {
    u64 d; asm("fma.rn.f32x2 %0, %1, %2, %3;" : "=l"(d) : "l"(a), "l"(b), "l"(c));
    return d;
}

__device__ __forceinline__ u32 smem_u32(const void* p) {
    u32 a;
    asm("{ .reg .u64 t; cvta.to.shared.u64 t, %1; cvt.u32.u64 %0, t; }"
        : "=r"(a) : "l"(p));
    return a;
}
__device__ __forceinline__ void cp_async8(u32 dst, const void* src) {
    asm volatile("cp.async.ca.shared.global [%0], [%1], 8;" :: "r"(dst), "l"(src));
}

__device__ __forceinline__ float sigmoid_fast(float x) {
    return __fdividef(1.0f, 1.0f + __expf(-x));
}
__device__ __forceinline__ float tanh_fast(float x) {
    return __fdividef(2.0f, 1.0f + __expf(-2.0f * x)) - 1.0f;
}

__global__ __launch_bounds__(128, 2)
void lstm_warp_kernel(
    const float* __restrict__ x,     // [B, T, 8]
    const float* __restrict__ W_ih,  // [128, 8]
    const float* __restrict__ W_hh,  // [128, 32]
    const float* __restrict__ b_ih,  // [128]
    const float* __restrict__ b_hh,  // [128]
    const float* __restrict__ W_fc,  // [1, 32]
    const float* __restrict__ b_fc,  // [1]
    float* __restrict__ out,         // [B]
    int B)
{
    // x staging: per warp, double-buffered 8-step chunks (256 B each)
    __shared__ __align__(16) float xs[4][2][CH * IN_SZ];
    // h broadcast staging, double-buffered per step parity
    __shared__ __align__(8) float hbuf[4][2][HID];

    const int wib  = threadIdx.x >> 5;
    const int warp = blockIdx.x * 4 + wib;
    const int lane = threadIdx.x & 31;
    if (warp >= B) return;

    // ---- register-resident packed weights: lane j owns hidden unit j ----
    u64 whhp[4][HID / 2];
    u64 wihp[4][IN_SZ / 2];
    u64 biasp[4];
    const u64* whh64 = reinterpret_cast<const u64*>(W_hh);
    const u64* wih64 = reinterpret_cast<const u64*>(W_ih);
#pragma unroll
    for (int g = 0; g < 4; g++) {
        const int row = g * HID + lane;
        biasp[g] = pack2(b_ih[row] + b_hh[row], 0.0f);
#pragma unroll
        for (int d = 0; d < IN_SZ / 2; d++) wihp[g][d] = wih64[row * (IN_SZ / 2) + d];
#pragma unroll
        for (int k = 0; k < HID / 2; k++)  whhp[g][k] = whh64[row * (HID / 2) + k];
    }

    // per-lane global source: 8 B per lane covers one 256 B chunk per warp
    const float* xw = x + (size_t)warp * ((size_t)T_STEPS * IN_SZ);

    // ---- prologue: prefetch chunks 0 and 1 ----
    {
        u32 d0 = smem_u32(&xs[wib][0][lane * 2]);
        cp_async8(d0, xw + 0 * (CH * IN_SZ) + lane * 2);
        asm volatile("cp.async.commit_group;");
        u32 d1 = smem_u32(&xs[wib][1][lane * 2]);
        cp_async8(d1, xw + 1 * (CH * IN_SZ) + lane * 2);
        asm volatile("cp.async.commit_group;");
    }

    float h = 0.0f, c = 0.0f;
    // xacc[g]: bias + x(t)·W_ih, prepared one step AHEAD so the 16 FMA2s
    // overlap the previous step's MUFU activation tail.
    u64 xacc0, xacc1, xacc2, xacc3;
    int t = 0;

#pragma unroll 1
    for (int ck = 0; ck < NCHUNK; ck++) {
        asm volatile("cp.async.wait_group 1;");   // chunk ck has landed
        __syncwarp();
        const u64* xb = reinterpret_cast<const u64*>(xs[wib][ck & 1]);

        // boundary: prepare xacc for the first step of this chunk
        {
            xacc0 = biasp[0]; xacc1 = biasp[1]; xacc2 = biasp[2]; xacc3 = biasp[3];
#pragma unroll
            for (int d = 0; d < IN_SZ / 2; d++) {
                const u64 xv = xb[d];
                xacc0 = fma2(wihp[0][d], xv, xacc0);
                xacc1 = fma2(wihp[1][d], xv, xacc1);
                xacc2 = fma2(wihp[2][d], xv, xacc2);
                xacc3 = fma2(wihp[3][d], xv, xacc3);
            }
        }

#pragma unroll
        for (int s = 0; s < CH; s++, t++) {
            // broadcast h through smem
            float* hb = hbuf[wib][t & 1];
            hb[lane] = h;
            __syncwarp();

            // consume the pre-computed input+bias accumulators
            u64 a0 = xacc0, a1 = xacc1, a2 = xacc2, a3 = xacc3;

            // recurrence: 16 pair iterations, 4 independent FMA2 chains
            const u64* hp = reinterpret_cast<const u64*>(hb);
#pragma unroll
            for (int k = 0; k < HID / 2; k++) {
                const u64 hk = hp[k];
                a0 = fma2(whhp[0][k], hk, a0);
                a1 = fma2(whhp[1][k], hk, a1);
                a2 = fma2(whhp[2][k], hk, a2);
                a3 = fma2(whhp[3][k], hk, a3);
            }

            float i0, i1, f0, f1, g0, g1, o0, o1;
            unpack2(a0, i0, i1);
            unpack2(a1, f0, f1);
            unpack2(a2, g0, g1);
            unpack2(a3, o0, o1);

            // activations (MUFU-heavy tail) ...
            const float ig = sigmoid_fast(i0 + i1);
            const float fg = sigmoid_fast(f0 + f1);
            const float gg = tanh_fast(g0 + g1);
            const float og = sigmoid_fast(o0 + o1);

            // ... overlapped with next step's input-gate FMAs (independent of h)
            if (s < CH - 1) {
                xacc0 = biasp[0]; xacc1 = biasp[1]; xacc2 = biasp[2]; xacc3 = biasp[3];
#pragma unroll
                for (int d = 0; d < IN_SZ / 2; d++) {
                    const u64 xv = xb[(s + 1) * (IN_SZ / 2) + d];
                    xacc0 = fma2(wihp[0][d], xv, xacc0);
                    xacc1 = fma2(wihp[1][d], xv, xacc1);
                    xacc2 = fma2(wihp[2][d], xv, xacc2);
                    xacc3 = fma2(wihp[3][d], xv, xacc3);
                }
            }

            c = fmaf(fg, c, ig * gg);
            h = og * tanh_fast(c);
        }

        // prefetch chunk ck+2 into the buffer we just finished reading
        if (ck + 2 < NCHUNK) {
            u32 dst = smem_u32(&xs[wib][ck & 1][lane * 2]);
            cp_async8(dst, xw + (ck + 2) * (CH * IN_SZ) + lane * 2);
        }
        asm volatile("cp.async.commit_group;");   // commit (possibly empty) group
    }

    // ---- final FC ----
    float v = h * W_fc[lane];
#pragma unroll
    for (int off = 16; off; off >>= 1)
        v += __shfl_xor_sync(0xffffffffu, v, off);
    if (lane == 0) out[warp] = v + b_fc[0];
}

extern "C" void kernel_launch(void* const* d_in, const int* in_sizes, int n_in,
                              void* d_out, int out_size) {
    const float* x    = (const float*)d_in[0];
    const float* W_ih = (const float*)d_in[1];
    const float* W_hh = (const float*)d_in[2];
    const float* b_ih = (const float*)d_in[3];
    const float* b_hh = (const float*)d_in[4];
    const float* W_fc = (const float*)d_in[5];
    const float* b_fc = (const float*)d_in[6];
    float* out = (float*)d_out;

    const int B = in_sizes[0] / (T_STEPS * IN_SZ);   // 8192
    const int blocks = (B + 3) / 4;                  // 4 warps / block
    lstm_warp_kernel<<<blocks, 128>>>(x, W_ih, W_hh, b_ih, b_hh, W_fc, b_fc, out, B);
}